// round 2
// baseline (speedup 1.0000x reference)
#include <cuda_runtime.h>
#include <cstdint>

// Problem sizes (fixed)
#define B_ROWS 16384
#define EMB    1024
#define HD     128
#define NJ     11              // Taylor terms j = 0..10
#define K2     (NJ*HD)         // 1408

// Scratch (device globals: allocation-free per harness rules)
__device__ float g_Y[2*B_ROWS*HD];     // [32768,128] projections (even row=values, odd=mask)
__device__ float g_U[B_ROWS*K2];       // [16384,1408]
__device__ float g_CsT[HD*K2];         // [n=k_out(128), j*128+h]  (B-matrix for GEMM2, K-major)
__device__ float g_sigma[K2];          // sigma[j*128+h] = sum_k c^j/j!

__constant__ float c_invfact[NJ] = {
    1.0f, 1.0f, 0.5f, 1.0f/6.0f, 1.0f/24.0f, 1.0f/120.0f, 1.0f/720.0f,
    1.0f/5040.0f, 1.0f/40320.0f, 1.0f/362880.0f, 1.0f/3628800.0f
};

// ---------------------------------------------------------------- prologue
// Build CsT[k][j*128+h] = cov[h][k]^j / j!  and  sigma[j][h] = sum_k of that.
__global__ void k_build_cs(const float* __restrict__ cov)
{
    int h = blockIdx.x;        // 0..127
    int k = threadIdx.x;       // 0..127
    __shared__ float red[HD];
    float c = cov[h*HD + k];
    float p = 1.0f;
    #pragma unroll
    for (int j = 0; j < NJ; j++) {
        float val = p * c_invfact[j];
        g_CsT[k*K2 + j*HD + h] = val;
        red[k] = val;
        __syncthreads();
        #pragma unroll
        for (int s = 64; s > 0; s >>= 1) {
            if (k < s) red[k] += red[k + s];
            __syncthreads();
        }
        if (k == 0) g_sigma[j*HD + h] = red[0];
        __syncthreads();
        p *= c;
    }
}

// ---------------------------------------------------------------- GEMM (tf32 mma.sync)
__device__ __forceinline__ void mma_tf32(float* c, const uint32_t* a, const uint32_t* b)
{
    asm volatile(
        "mma.sync.aligned.m16n8k8.row.col.f32.tf32.tf32.f32 "
        "{%0,%1,%2,%3},{%4,%5,%6,%7},{%8,%9},{%0,%1,%2,%3};\n"
        : "+f"(c[0]), "+f"(c[1]), "+f"(c[2]), "+f"(c[3])
        : "r"(a[0]), "r"(a[1]), "r"(a[2]), "r"(a[3]), "r"(b[0]), "r"(b[1]));
}

__device__ __forceinline__ void cpasync16(uint32_t d, const void* s)
{
    asm volatile("cp.async.cg.shared.global [%0], [%1], 16;\n" :: "r"(d), "l"(s));
}
__device__ __forceinline__ void cp_commit() { asm volatile("cp.async.commit_group;\n"); }
template<int N> __device__ __forceinline__ void cp_wait() { asm volatile("cp.async.wait_group %0;\n" :: "n"(N)); }

// C[M,128] = A[M,K] * Bm[128,K]^T (+bias).  K % 32 == 0, M % 128 == 0.
// mode 0: A=Aext(x), Bm=Bext(W), C=g_Y.   mode 1: A=g_U, Bm=g_CsT, C=Cext(out).
// Tiling: block 128x128, BK=32, 256 threads = 8 warps in 4(M) x 2(N); warp tile 32x64.
#define SMEM_TILE (128*36)     // floats per [128][36] buffer
__global__ void k_gemm_tf32(int mode,
                            const float* __restrict__ Aext,
                            const float* __restrict__ Bext,
                            float* __restrict__ Cext,
                            int M, int K, const float* __restrict__ bias)
{
    const float* A  = (mode == 0) ? Aext : g_U;
    const float* Bm = (mode == 0) ? Bext : g_CsT;
    float*       C  = (mode == 0) ? g_Y  : Cext;

    extern __shared__ float sm[];
    float* As = sm;                    // [2][128][36]
    float* Bs = sm + 2*SMEM_TILE;      // [2][128][36]

    const int tid  = threadIdx.x;
    const int warp = tid >> 5, lane = tid & 31;
    const int wm = warp & 3, wn = warp >> 2;   // 4 x 2 warp grid
    const int g  = lane >> 2, tg = lane & 3;
    const int mBase = blockIdx.x * 128;

    const uint32_t AsAddr = (uint32_t)__cvta_generic_to_shared(As);
    const uint32_t BsAddr = (uint32_t)__cvta_generic_to_shared(Bs);

    auto loadTile = [&](int buf, int k0) {
        #pragma unroll
        for (int i = 0; i < 4; i++) {
            int idx = tid + i * 256;           // 0..1023 float4 slots
            int row = idx >> 3;
            int kv  = (idx & 7) * 4;
            cpasync16(AsAddr + (uint32_t)((buf*SMEM_TILE + row*36 + kv) << 2),
                      A  + (size_t)(mBase + row) * K + k0 + kv);
            cpasync16(BsAddr + (uint32_t)((buf*SMEM_TILE + row*36 + kv) << 2),
                      Bm + (size_t)row * K + k0 + kv);
        }
        cp_commit();
    };

    float acc[2][8][4];
    #pragma unroll
    for (int mt = 0; mt < 2; mt++)
        #pragma unroll
        for (int nt = 0; nt < 8; nt++)
            #pragma unroll
            for (int r = 0; r < 4; r++) acc[mt][nt][r] = 0.0f;

    const int nCh = K / 32;
    loadTile(0, 0);

    for (int cI = 0; cI < nCh; cI++) {
        if (cI + 1 < nCh) { loadTile((cI + 1) & 1, (cI + 1) * 32); cp_wait<1>(); }
        else              { cp_wait<0>(); }
        __syncthreads();

        const float* as = As + (cI & 1) * SMEM_TILE;
        const float* bs = Bs + (cI & 1) * SMEM_TILE;

        #pragma unroll
        for (int ks = 0; ks < 4; ks++) {
            const int k = ks * 8;
            uint32_t af[2][4], bf[8][2];
            #pragma unroll
            for (int mt = 0; mt < 2; mt++) {
                const int m0 = wm*32 + mt*16;
                af[mt][0] = __float_as_uint(as[(m0 + g    ) * 36 + k + tg    ]);
                af[mt][1] = __float_as_uint(as[(m0 + g + 8) * 36 + k + tg    ]);
                af[mt][2] = __float_as_uint(as[(m0 + g    ) * 36 + k + tg + 4]);
                af[mt][3] = __float_as_uint(as[(m0 + g + 8) * 36 + k + tg + 4]);
            }
            #pragma unroll
            for (int nt = 0; nt < 8; nt++) {
                const int n0 = wn*64 + nt*8;
                bf[nt][0] = __float_as_uint(bs[(n0 + g) * 36 + k + tg    ]);
                bf[nt][1] = __float_as_uint(bs[(n0 + g) * 36 + k + tg + 4]);
            }
            #pragma unroll
            for (int mt = 0; mt < 2; mt++)
                #pragma unroll
                for (int nt = 0; nt < 8; nt++)
                    mma_tf32(acc[mt][nt], af[mt], bf[nt]);
        }
        __syncthreads();
    }

    // epilogue
    #pragma unroll
    for (int mt = 0; mt < 2; mt++) {
        const int r0 = mBase + wm*32 + mt*16 + g;
        #pragma unroll
        for (int nt = 0; nt < 8; nt++) {
            const int c0 = wn*64 + nt*8 + tg*2;
            float b0 = 0.0f, b1 = 0.0f;
            if (bias) { b0 = bias[c0]; b1 = bias[c0 + 1]; }
            float2 v0 = make_float2(acc[mt][nt][0] + b0, acc[mt][nt][1] + b1);
            float2 v1 = make_float2(acc[mt][nt][2] + b0, acc[mt][nt][3] + b1);
            *(float2*)(C + (size_t)r0       * HD + c0) = v0;
            *(float2*)(C + (size_t)(r0 + 8) * HD + c0) = v1;
        }
    }
}

// ---------------------------------------------------------------- middle
// Per (b,h): powers of m, D = sum_j m^j * sigma[j][h], w = v/D, U[b][j*128+h] = w*m^j.
__global__ void k_middle()
{
    __shared__ float s_sig[K2];
    const int tid = threadIdx.x;
    for (int i = tid; i < K2; i += 256) s_sig[i] = g_sigma[i];
    __syncthreads();

    const int gid = blockIdx.x * 256 + tid;
    const int b = gid >> 7;
    const int h = gid & 127;

    const float v = g_Y[(size_t)(2*b    ) * HD + h];
    const float m = g_Y[(size_t)(2*b + 1) * HD + h];

    float pw[NJ];
    float p = 1.0f, D = 0.0f;
    #pragma unroll
    for (int j = 0; j < NJ; j++) {
        pw[j] = p;
        D = fmaf(p, s_sig[j*HD + h], D);
        p *= m;
    }
    const float w = v / D;
    #pragma unroll
    for (int j = 0; j < NJ; j++)
        g_U[(size_t)b * K2 + j*HD + h] = w * pw[j];
}

// ---------------------------------------------------------------- launch
extern "C" void kernel_launch(void* const* d_in, const int* in_sizes, int n_in,
                              void* d_out, int out_size)
{
    const float* x    = (const float*)d_in[0];   // [16384,2,1024]
    const float* W    = (const float*)d_in[1];   // [128,1024]
    const float* cov  = (const float*)d_in[2];   // [128,128]
    const float* bias = (const float*)d_in[3];   // [128]
    float* out = (float*)d_out;                  // [16384,128]

    cudaFuncSetAttribute(k_gemm_tf32, cudaFuncAttributeMaxDynamicSharedMemorySize,
                         4 * 4 * SMEM_TILE);     // 73728 bytes

    k_build_cs<<<HD, HD>>>(cov);
    k_gemm_tf32<<<2*B_ROWS/128, 256, 4*4*SMEM_TILE>>>(0, x, W, nullptr, 2*B_ROWS, EMB, nullptr);
    k_middle<<<B_ROWS*HD/256, 256>>>();
    k_gemm_tf32<<<B_ROWS/128, 256, 4*4*SMEM_TILE>>>(1, nullptr, nullptr, out, B_ROWS, K2, bias);
}

// round 4
// speedup vs baseline: 1.3999x; 1.3999x over previous
#include <cuda_runtime.h>
#include <cstdint>

// ---------------- problem sizes (fixed) ----------------
#define B_ROWS 16384
#define EMB    1024
#define HD     128
#define NJ     11              // Taylor terms j = 0..10
#define K2     (NJ*HD)         // 1408

// ---------------- scratch (device globals; allocation-free) ----------------
__device__ float g_Y[2*B_ROWS*HD];     // [32768,128] projections (even=values, odd=mask)
__device__ float g_CsT[HD*K2];         // [k_out(128)][j*128+h]  (GEMM2 B, K-major)
__device__ float g_sigma[K2];          // sigma[j*128+h] = sum_k c^j/j!

__constant__ float c_invfact[NJ] = {
    1.0f, 1.0f, 0.5f, 1.0f/6.0f, 1.0f/24.0f, 1.0f/120.0f, 1.0f/720.0f,
    1.0f/5040.0f, 1.0f/40320.0f, 1.0f/362880.0f, 1.0f/3628800.0f
};

// ---------------- helpers ----------------
__device__ __forceinline__ uint32_t cvta_sh(const void* p) {
    uint32_t a;
    asm("{ .reg .u64 t; cvta.to.shared.u64 t, %1; cvt.u32.u64 %0, t; }" : "=r"(a) : "l"(p));
    return a;
}
__device__ __forceinline__ void cpasync16(uint32_t d, const void* s)
{
    asm volatile("cp.async.cg.shared.global [%0], [%1], 16;\n" :: "r"(d), "l"(s));
}
__device__ __forceinline__ void cp_commit() { asm volatile("cp.async.commit_group;\n" ::: "memory"); }
template<int N> __device__ __forceinline__ void cp_wait() { asm volatile("cp.async.wait_group %0;\n" :: "n"(N) : "memory"); }

__device__ __forceinline__ void ldm_x4(uint32_t addr, uint32_t* r)
{
    asm volatile("ldmatrix.sync.aligned.m8n8.x4.shared.b16 {%0,%1,%2,%3}, [%4];"
                 : "=r"(r[0]), "=r"(r[1]), "=r"(r[2]), "=r"(r[3]) : "r"(addr));
}
__device__ __forceinline__ void mma_tf32(float* c, const uint32_t* a, uint32_t b0, uint32_t b1)
{
    asm volatile(
        "mma.sync.aligned.m16n8k8.row.col.f32.tf32.tf32.f32 "
        "{%0,%1,%2,%3},{%4,%5,%6,%7},{%8,%9},{%0,%1,%2,%3};\n"
        : "+f"(c[0]), "+f"(c[1]), "+f"(c[2]), "+f"(c[3])
        : "r"(a[0]), "r"(a[1]), "r"(a[2]), "r"(a[3]), "r"(b0), "r"(b1));
}

// ---------------- prologue: CsT[k][j*128+h] = cov[h][k]^j/j!, sigma = sums over k ----------------
__global__ void k_build_cs(const float* __restrict__ cov)
{
    int h = blockIdx.x;        // 0..127
    int k = threadIdx.x;       // 0..127
    __shared__ float red[HD];
    float c = cov[h*HD + k];
    float p = 1.0f;
    #pragma unroll
    for (int j = 0; j < NJ; j++) {
        float val = p * c_invfact[j];
        g_CsT[k*K2 + j*HD + h] = val;
        red[k] = val;
        __syncthreads();
        #pragma unroll
        for (int s = 64; s > 0; s >>= 1) {
            if (k < s) red[k] += red[k + s];
            __syncthreads();
        }
        if (k == 0) g_sigma[j*HD + h] = red[0];
        __syncthreads();
        p *= c;
    }
}

// =====================================================================
// GEMM1: g_Y[32768,128] = x[32768,1024] @ W[128,1024]^T  (tf32 mma.sync)
// Block tile 128x128, BK=32, 2-stage cp.async, 8 warps (4M x 2N), warp 32x64.
// Fragment feed via ldmatrix.m8n8.x4.b16 (tf32-fragment-compatible layout).
// =====================================================================
#define TILE_F 4608            // 128*36 floats per stage buffer
__global__ void __launch_bounds__(256, 2)
k_gemm(const float* __restrict__ A, const float* __restrict__ Bm)
{
    extern __shared__ __align__(16) float sm[];
    float* As = sm;                 // [2][128][36]
    float* Bs = sm + 2*TILE_F;      // [2][128][36]

    const int tid = threadIdx.x, lane = tid & 31, warp = tid >> 5;
    const int wm = warp & 3, wn = warp >> 2;
    const int mBase = blockIdx.x * 128;
    const uint32_t AsA = cvta_sh(As), BsA = cvta_sh(Bs);

    auto load = [&](int c) {
        const int buf = c & 1, k0 = c * 32;
        #pragma unroll
        for (int i = 0; i < 4; i++) {
            int idx = tid + i * 256, r = idx >> 3, kv = (idx & 7) * 4;
            uint32_t off = (uint32_t)((buf*TILE_F + r*36 + kv) << 2);
            cpasync16(AsA + off, A  + (size_t)(mBase + r) * EMB + k0 + kv);
            cpasync16(BsA + off, Bm + (size_t)r * EMB + k0 + kv);
        }
        cp_commit();
    };

    float acc[2][8][4] = {};

    // ldmatrix address components
    const uint32_t rSel = lane & 15;
    const uint32_t cSel = ((lane >> 4) & 1) * 4;
    const uint32_t aOff0 = ((wm*32 + rSel)*36 + cSel) * 4;
    const uint32_t aOff1 = aOff0 + 16*36*4;
    uint32_t bOff[4];
    #pragma unroll
    for (int p = 0; p < 4; p++) bOff[p] = ((wn*64 + p*16 + rSel)*36 + cSel) * 4;

    load(0);
    const int nCh = EMB / 32;
    for (int c = 0; c < nCh; c++) {
        if (c + 1 < nCh) { load(c + 1); cp_wait<1>(); } else cp_wait<0>();
        __syncthreads();
        const uint32_t aB = AsA + (uint32_t)(((c & 1) * TILE_F) << 2);
        const uint32_t bB = BsA + (uint32_t)(((c & 1) * TILE_F) << 2);
        #pragma unroll
        for (int ks = 0; ks < 4; ks++) {
            uint32_t a0[4], a1[4], bq[4][4];
            ldm_x4(aB + aOff0 + ks*32, a0);
            ldm_x4(aB + aOff1 + ks*32, a1);
            #pragma unroll
            for (int p = 0; p < 4; p++) ldm_x4(bB + bOff[p] + ks*32, bq[p]);
            #pragma unroll
            for (int nt = 0; nt < 8; nt++) {
                const uint32_t b0 = bq[nt >> 1][nt & 1];
                const uint32_t b1 = bq[nt >> 1][2 + (nt & 1)];
                mma_tf32(acc[0][nt], a0, b0, b1);
                mma_tf32(acc[1][nt], a1, b0, b1);
            }
        }
        __syncthreads();
    }

    // epilogue -> g_Y
    const int g = lane >> 2, tg = lane & 3;
    #pragma unroll
    for (int mt = 0; mt < 2; mt++) {
        const size_t r0 = (size_t)(mBase + wm*32 + mt*16 + g);
        #pragma unroll
        for (int nt = 0; nt < 8; nt++) {
            const int c0 = wn*64 + nt*8 + tg*2;
            *(float2*)(g_Y + r0       * HD + c0) = make_float2(acc[mt][nt][0], acc[mt][nt][1]);
            *(float2*)(g_Y + (r0 + 8) * HD + c0) = make_float2(acc[mt][nt][2], acc[mt][nt][3]);
        }
    }
}

// =====================================================================
// k_out: fused (middle + GEMM2).
// out[128-row tile][128] = sum_j (w*m^j)[r][h] * CsT[k][j*128+h] + bias
// A-operand generated in smem: cur[r][h] starts at w = v/D, *= m per j.
// B chunks (CsT, 32 K-cols) streamed via 2-stage cp.async (L2-resident).
// =====================================================================
#define KO_B_OFF   0            // [2][128][36] floats  = 36864 B
#define KO_M_OFF   36864        // [128][132] floats    = 67584 B
#define KO_CUR_OFF 104448       // [128][132] floats    = 67584 B
#define KO_SIG_OFF 172032       // [1408] floats        = 5632 B
#define KO_SMEM    177664

__global__ void __launch_bounds__(256, 1)
k_out(const float* __restrict__ bias, float* __restrict__ out)
{
    extern __shared__ __align__(16) char smc[];
    float* Bs   = (float*)(smc + KO_B_OFF);
    float* m_s  = (float*)(smc + KO_M_OFF);
    float* curS = (float*)(smc + KO_CUR_OFF);
    float* sigS = (float*)(smc + KO_SIG_OFF);

    const int tid = threadIdx.x, lane = tid & 31, warp = tid >> 5;
    const int wm = warp & 3, wn = warp >> 2;
    const int mBase = blockIdx.x * 128;
    const uint32_t BsA = cvta_sh(Bs), curA = cvta_sh(curS);

    auto loadB = [&](int c) {
        const int buf = c & 1;
        #pragma unroll
        for (int i = 0; i < 4; i++) {
            int idx = tid + i * 256, r = idx >> 3, kv = (idx & 7) * 4;
            cpasync16(BsA + (uint32_t)((buf*TILE_F + r*36 + kv) << 2),
                      g_CsT + (size_t)r * K2 + c*32 + kv);
        }
        cp_commit();
    };

    // sigma to smem + first B chunk in flight
    for (int i = tid; i < K2; i += 256) sigS[i] = g_sigma[i];
    loadB(0);
    __syncthreads();

    // init: m_s = m, curS = w = v / D   (D = sum_j m^j * sigma[j][h])
    for (int it = 0; it < 64; it++) {
        const int e = tid + it * 256;
        const int r = e >> 7, h = e & 127;
        const float v = g_Y[(size_t)(2*(mBase + r)    ) * HD + h];
        const float m = g_Y[(size_t)(2*(mBase + r) + 1) * HD + h];
        float p = 1.0f, D = 0.0f;
        #pragma unroll
        for (int j = 0; j < NJ; j++) { D = fmaf(p, sigS[j*HD + h], D); p *= m; }
        m_s [r*132 + h] = m;
        curS[r*132 + h] = v / D;
    }
    __syncthreads();

    float acc[2][8][4] = {};

    const uint32_t rSel = lane & 15;
    const uint32_t cSel = ((lane >> 4) & 1) * 4;
    const uint32_t aOff0 = ((wm*32 + rSel)*132 + cSel) * 4;  // stride 132 floats
    const uint32_t aOff1 = aOff0 + 16*132*4;
    uint32_t bOff[4];
    #pragma unroll
    for (int p = 0; p < 4; p++) bOff[p] = ((wn*64 + p*16 + rSel)*36 + cSel) * 4;

    const int nCh = K2 / 32;   // 44
    for (int c = 0; c < nCh; c++) {
        if (c + 1 < nCh) { loadB(c + 1); cp_wait<1>(); } else cp_wait<0>();
        __syncthreads();
        const uint32_t aB = curA + (uint32_t)((c & 3) * 128);   // +32 floats per h-block
        const uint32_t bB = BsA + (uint32_t)(((c & 1) * TILE_F) << 2);
        #pragma unroll
        for (int ks = 0; ks < 4; ks++) {
            uint32_t a0[4], a1[4], bq[4][4];
            ldm_x4(aB + aOff0 + ks*32, a0);
            ldm_x4(aB + aOff1 + ks*32, a1);
            #pragma unroll
            for (int p = 0; p < 4; p++) ldm_x4(bB + bOff[p] + ks*32, bq[p]);
            #pragma unroll
            for (int nt = 0; nt < 8; nt++) {
                const uint32_t b0 = bq[nt >> 1][nt & 1];
                const uint32_t b1 = bq[nt >> 1][2 + (nt & 1)];
                mma_tf32(acc[0][nt], a0, b0, b1);
                mma_tf32(acc[1][nt], a1, b0, b1);
            }
        }
        __syncthreads();
        if ((c & 3) == 3 && c < nCh - 1) {          // j boundary: cur *= m
            float4* cu = (float4*)curS;
            float4* mv = (float4*)m_s;
            #pragma unroll 4
            for (int it = 0; it < 16; it++) {
                const int e = tid + it * 256;       // 0..4095 float4 slots of data
                const int r = e >> 5, s = e & 31;   // 32 data-float4 per row, stride 33
                const int off = r*33 + s;
                float4 a = cu[off];
                const float4 b = mv[off];
                a.x *= b.x; a.y *= b.y; a.z *= b.z; a.w *= b.w;
                cu[off] = a;
            }
            __syncthreads();
        }
    }

    // epilogue: + bias -> out
    const int g = lane >> 2, tg = lane & 3;
    #pragma unroll
    for (int mt = 0; mt < 2; mt++) {
        const size_t r0 = (size_t)(mBase + wm*32 + mt*16 + g);
        #pragma unroll
        for (int nt = 0; nt < 8; nt++) {
            const int c0 = wn*64 + nt*8 + tg*2;
            const float b0 = bias[c0], b1 = bias[c0 + 1];
            *(float2*)(out + r0       * HD + c0) = make_float2(acc[mt][nt][0] + b0, acc[mt][nt][1] + b1);
            *(float2*)(out + (r0 + 8) * HD + c0) = make_float2(acc[mt][nt][2] + b0, acc[mt][nt][3] + b1);
        }
    }
}

// ---------------- launch ----------------
extern "C" void kernel_launch(void* const* d_in, const int* in_sizes, int n_in,
                              void* d_out, int out_size)
{
    const float* x    = (const float*)d_in[0];   // [16384,2,1024]
    const float* W    = (const float*)d_in[1];   // [128,1024]
    const float* cov  = (const float*)d_in[2];   // [128,128]
    const float* bias = (const float*)d_in[3];   // [128]
    float* out = (float*)d_out;                  // [16384,128]

    cudaFuncSetAttribute(k_gemm, cudaFuncAttributeMaxDynamicSharedMemorySize, 4*TILE_F*4);
    cudaFuncSetAttribute(k_out,  cudaFuncAttributeMaxDynamicSharedMemorySize, KO_SMEM);

    k_build_cs<<<HD, HD>>>(cov);
    k_gemm<<<2*B_ROWS/128, 256, 4*TILE_F*4>>>(x, W);
    k_out<<<B_ROWS/128, 256, KO_SMEM>>>(bias, out);
}

// round 10
// speedup vs baseline: 1.4147x; 1.0106x over previous
#include <cuda_runtime.h>
#include <cstdint>

// ---------------- problem sizes (fixed) ----------------
#define B_ROWS 16384
#define EMB    1024
#define HD     128
#define NJ     11              // Taylor terms j = 0..10
#define K2     (NJ*HD)         // 1408

// ---------------- scratch (device globals; allocation-free) ----------------
__device__ float g_Y[2*B_ROWS*HD];     // [32768,128] projections (even=values, odd=mask)
__device__ float g_CsT[HD*K2];         // [k_out(128)][j*128+h]  (GEMM2 B, K-major)
__device__ float g_sigma[K2];          // sigma[j*128+h] = sum_k c^j/j!

__constant__ float c_invfact[NJ] = {
    1.0f, 1.0f, 0.5f, 1.0f/6.0f, 1.0f/24.0f, 1.0f/120.0f, 1.0f/720.0f,
    1.0f/5040.0f, 1.0f/40320.0f, 1.0f/362880.0f, 1.0f/3628800.0f
};

// ---------------- helpers ----------------
__device__ __forceinline__ uint32_t cvta_sh(const void* p) {
    uint32_t a;
    asm("{ .reg .u64 t; cvta.to.shared.u64 t, %1; cvt.u32.u64 %0, t; }" : "=r"(a) : "l"(p));
    return a;
}
__device__ __forceinline__ void cpasync16(uint32_t d, const void* s)
{
    asm volatile("cp.async.cg.shared.global [%0], [%1], 16;\n" :: "r"(d), "l"(s));
}
__device__ __forceinline__ void cp_commit() { asm volatile("cp.async.commit_group;\n" ::: "memory"); }
template<int N> __device__ __forceinline__ void cp_wait() { asm volatile("cp.async.wait_group %0;\n" :: "n"(N) : "memory"); }

__device__ __forceinline__ void ldm_x4(uint32_t addr, uint32_t* r)
{
    asm volatile("ldmatrix.sync.aligned.m8n8.x4.shared.b16 {%0,%1,%2,%3}, [%4];"
                 : "=r"(r[0]), "=r"(r[1]), "=r"(r[2]), "=r"(r[3]) : "r"(addr));
}
__device__ __forceinline__ void mma_tf32(float* c, const uint32_t* a, uint32_t b0, uint32_t b1)
{
    asm volatile(
        "mma.sync.aligned.m16n8k8.row.col.f32.tf32.tf32.f32 "
        "{%0,%1,%2,%3},{%4,%5,%6,%7},{%8,%9},{%0,%1,%2,%3};\n"
        : "+f"(c[0]), "+f"(c[1]), "+f"(c[2]), "+f"(c[3])
        : "r"(a[0]), "r"(a[1]), "r"(a[2]), "r"(a[3]), "r"(b0), "r"(b1));
}

// ---------------- prologue: CsT (coalesced) + sigma (shfl reduce) ----------------
__global__ void k_prep(const float* __restrict__ cov)
{
    const int bid = blockIdx.x, tid = threadIdx.x;
    if (bid < 128) {
        // g_CsT[k][j*128+h] = cov[h][k]^j / j!; block = k, thread = h (coalesced writes)
        const int k = bid, h = tid;
        float c = cov[h*HD + k];
        float p = 1.0f;
        #pragma unroll
        for (int j = 0; j < NJ; j++) {
            g_CsT[(size_t)k*K2 + j*HD + h] = p * c_invfact[j];
            p *= c;
        }
    } else {
        // sigma[j*128+h] = sum_k cov[h][k]^j / j!; block = h, thread = k
        const int h = bid - 128, k = tid;
        __shared__ float s_part[4];
        float c = cov[h*HD + k];
        float p = 1.0f;
        #pragma unroll
        for (int j = 0; j < NJ; j++) {
            float v = p * c_invfact[j];
            #pragma unroll
            for (int s = 16; s > 0; s >>= 1) v += __shfl_xor_sync(0xffffffffu, v, s);
            if ((k & 31) == 0) s_part[k >> 5] = v;
            __syncthreads();
            if (k == 0) g_sigma[j*HD + h] = s_part[0] + s_part[1] + s_part[2] + s_part[3];
            __syncthreads();
            p *= c;
        }
    }
}

// =====================================================================
// GEMM1 (tf32): g_Y[32768,128] = x[32768,1024] @ W[128,1024]^T
// Block 128x128, BK=32, 256 thr (8 warps: 4M x 2N, warp 32x64).
// 3-stage cp.async for A and B; ONE barrier per chunk; ldmatrix feed.
// =====================================================================
#define TILE_F 4608            // 128*36 floats per stage buffer (18432 B)
#define G1_SMEM (6*TILE_F*4)   // 3 stages A + 3 stages B = 110592 B

__global__ void __launch_bounds__(256, 2)
k_gemm(const float* __restrict__ A, const float* __restrict__ Bm)
{
    extern __shared__ __align__(16) float sm[];
    const uint32_t AsA = cvta_sh(sm);                  // 3 stages
    const uint32_t BsA = AsA + 3*TILE_F*4;             // 3 stages

    const int tid = threadIdx.x, lane = tid & 31, warp = tid >> 5;
    const int wm = warp & 3, wn = warp >> 2;
    const int mBase = blockIdx.x * 128;

    auto load = [&](int c) {
        const int st = c % 3, k0 = c * 32;
        #pragma unroll
        for (int i = 0; i < 4; i++) {
            int idx = tid + i * 256, r = idx >> 3, kv = (idx & 7) * 4;
            uint32_t off = (uint32_t)((st*TILE_F + r*36 + kv) << 2);
            cpasync16(AsA + off, A  + (size_t)(mBase + r) * EMB + k0 + kv);
            cpasync16(BsA + off, Bm + (size_t)r * EMB + k0 + kv);
        }
        cp_commit();
    };

    float acc[2][8][4] = {};

    const uint32_t rSel = lane & 15;
    const uint32_t cSel = ((lane >> 4) & 1) * 4;
    const uint32_t aOff0 = ((wm*32 + rSel)*36 + cSel) * 4;
    const uint32_t aOff1 = aOff0 + 16*36*4;
    uint32_t bOff[4];
    #pragma unroll
    for (int p = 0; p < 4; p++) bOff[p] = ((wn*64 + p*16 + rSel)*36 + cSel) * 4;

    const int nCh = EMB / 32;   // 32
    load(0); load(1);
    cp_wait<1>();
    __syncthreads();

    for (int c = 0; c < nCh; c++) {
        if (c + 2 < nCh) load(c + 2); else cp_commit();

        const uint32_t aB = AsA + (uint32_t)(((c % 3) * TILE_F) << 2);
        const uint32_t bB = BsA + (uint32_t)(((c % 3) * TILE_F) << 2);
        #pragma unroll
        for (int ks = 0; ks < 4; ks++) {
            uint32_t a0[4], a1[4], bq[4][4];
            ldm_x4(aB + aOff0 + ks*32, a0);
            ldm_x4(aB + aOff1 + ks*32, a1);
            #pragma unroll
            for (int p = 0; p < 4; p++) ldm_x4(bB + bOff[p] + ks*32, bq[p]);
            #pragma unroll
            for (int nt = 0; nt < 8; nt++) {
                const uint32_t b0 = bq[nt >> 1][nt & 1];
                const uint32_t b1 = bq[nt >> 1][2 + (nt & 1)];
                mma_tf32(acc[0][nt], a0, b0, b1);
                mma_tf32(acc[1][nt], a1, b0, b1);
            }
        }
        cp_wait<1>();
        __syncthreads();
    }

    // epilogue -> g_Y
    const int g = lane >> 2, tg = lane & 3;
    #pragma unroll
    for (int mt = 0; mt < 2; mt++) {
        const size_t r0 = (size_t)(mBase + wm*32 + mt*16 + g);
        #pragma unroll
        for (int nt = 0; nt < 8; nt++) {
            const int c0 = wn*64 + nt*8 + tg*2;
            *(float2*)(g_Y + r0       * HD + c0) = make_float2(acc[mt][nt][0], acc[mt][nt][1]);
            *(float2*)(g_Y + (r0 + 8) * HD + c0) = make_float2(acc[mt][nt][2], acc[mt][nt][3]);
        }
    }
}

// =====================================================================
// k_out (tf32): fused (softmax-normalize + GEMM2).
// out[128-tile][128] = sum_j (w*m^j)[r][h] * CsT[k][j*128+h] + bias
// cur tile fp32 in smem (exact power chain); B streamed, 3-stage, 1 barrier/chunk.
// =====================================================================
#define KO_BS_OFF   0                     // 3 x 18432 = 55296
#define KO_M_OFF    55296                 // fp32 [128][132] = 67584
#define KO_CUR_OFF  122880                // fp32 [128][132] = 67584
#define KO_SIG_OFF  190464                // fp32 [1408]     = 5632
#define KO_SMEM     196096

__global__ void __launch_bounds__(256, 1)
k_out(const float* __restrict__ bias, float* __restrict__ out)
{
    extern __shared__ __align__(16) char smc[];
    float* m_s  = (float*)(smc + KO_M_OFF);
    float* curS = (float*)(smc + KO_CUR_OFF);
    float* sigS = (float*)(smc + KO_SIG_OFF);

    const int tid = threadIdx.x, lane = tid & 31, warp = tid >> 5;
    const int wm = warp & 3, wn = warp >> 2;
    const int mBase = blockIdx.x * 128;
    const uint32_t BsA = cvta_sh(smc + KO_BS_OFF);
    const uint32_t curA = cvta_sh(curS);

    auto loadB = [&](int c) {
        const int st = c % 3;
        #pragma unroll
        for (int i = 0; i < 4; i++) {
            int idx = tid + i * 256, r = idx >> 3, kv = (idx & 7) * 4;
            cpasync16(BsA + (uint32_t)((st*TILE_F + r*36 + kv) << 2),
                      g_CsT + (size_t)r * K2 + c*32 + kv);
        }
        cp_commit();
    };

    for (int i = tid; i < K2; i += 256) sigS[i] = g_sigma[i];
    loadB(0); loadB(1);
    __syncthreads();          // *** THE FIX: sigS must be fully written before init reads it ***

    // init: m_s = m, curS = w = v / D   (D = sum_j m^j * sigma[j][h])
    #pragma unroll 4
    for (int it = 0; it < 64; it++) {
        const int e = tid + it * 256;
        const int r = e >> 7, h = e & 127;
        const float v = g_Y[(size_t)(2*(mBase + r)    ) * HD + h];
        const float m = g_Y[(size_t)(2*(mBase + r) + 1) * HD + h];
        float p = 1.0f, D = 0.0f;
        #pragma unroll
        for (int j = 0; j < NJ; j++) { D = fmaf(p, sigS[j*HD + h], D); p *= m; }
        m_s [r*132 + h] = m;
        curS[r*132 + h] = v / D;
    }
    cp_wait<1>();
    __syncthreads();

    float acc[2][8][4] = {};

    const uint32_t rSel = lane & 15;
    const uint32_t cSel = ((lane >> 4) & 1) * 4;
    const uint32_t aOff0 = ((wm*32 + rSel)*132 + cSel) * 4;  // stride 132 floats
    const uint32_t aOff1 = aOff0 + 16*132*4;
    uint32_t bOff[4];
    #pragma unroll
    for (int p = 0; p < 4; p++) bOff[p] = ((wn*64 + p*16 + rSel)*36 + cSel) * 4;

    const int nCh = K2 / 32;   // 44
    for (int c = 0; c < nCh; c++) {
        if (c + 2 < nCh) loadB(c + 2); else cp_commit();

        const uint32_t aB = curA + (uint32_t)((c & 3) * 128);   // +32 floats per h-block
        const uint32_t bB = BsA + (uint32_t)(((c % 3) * TILE_F) << 2);
        #pragma unroll
        for (int ks = 0; ks < 4; ks++) {
            uint32_t a0[4], a1[4], bq[4][4];
            ldm_x4(aB + aOff0 + ks*32, a0);
            ldm_x4(aB + aOff1 + ks*32, a1);
            #pragma unroll
            for (int p = 0; p < 4; p++) ldm_x4(bB + bOff[p] + ks*32, bq[p]);
            #pragma unroll
            for (int nt = 0; nt < 8; nt++) {
                const uint32_t b0 = bq[nt >> 1][nt & 1];
                const uint32_t b1 = bq[nt >> 1][2 + (nt & 1)];
                mma_tf32(acc[0][nt], a0, b0, b1);
                mma_tf32(acc[1][nt], a1, b0, b1);
            }
        }
        cp_wait<1>();
        __syncthreads();

        if ((c & 3) == 3 && c < nCh - 1) {          // j boundary: cur *= m
            float4* cu = (float4*)curS;
            float4* mv = (float4*)m_s;
            #pragma unroll 4
            for (int it = 0; it < 16; it++) {
                const int e = tid + it * 256;       // 0..4095 data float4 slots
                const int r = e >> 5, s = e & 31;   // 32 data-float4 per row, stride 33
                const int off = r*33 + s;
                float4 a = cu[off];
                const float4 b = mv[off];
                a.x *= b.x; a.y *= b.y; a.z *= b.z; a.w *= b.w;
                cu[off] = a;
            }
            __syncthreads();
        }
    }

    // epilogue: + bias -> out
    const int g = lane >> 2, tg = lane & 3;
    #pragma unroll
    for (int mt = 0; mt < 2; mt++) {
        const size_t r0 = (size_t)(mBase + wm*32 + mt*16 + g);
        #pragma unroll
        for (int nt = 0; nt < 8; nt++) {
            const int c0 = wn*64 + nt*8 + tg*2;
            const float b0 = bias[c0], b1 = bias[c0 + 1];
            *(float2*)(out + r0       * HD + c0) = make_float2(acc[mt][nt][0] + b0, acc[mt][nt][1] + b1);
            *(float2*)(out + (r0 + 8) * HD + c0) = make_float2(acc[mt][nt][2] + b0, acc[mt][nt][3] + b1);
        }
    }
}

// ---------------- launch ----------------
extern "C" void kernel_launch(void* const* d_in, const int* in_sizes, int n_in,
                              void* d_out, int out_size)
{
    const float* x    = (const float*)d_in[0];   // [16384,2,1024]
    const float* W    = (const float*)d_in[1];   // [128,1024]
    const float* cov  = (const float*)d_in[2];   // [128,128]
    const float* bias = (const float*)d_in[3];   // [128]
    float* out = (float*)d_out;                  // [16384,128]

    cudaFuncSetAttribute(k_gemm, cudaFuncAttributeMaxDynamicSharedMemorySize, G1_SMEM);
    cudaFuncSetAttribute(k_out,  cudaFuncAttributeMaxDynamicSharedMemorySize, KO_SMEM);

    k_prep<<<256, 128>>>(cov);
    k_gemm<<<2*B_ROWS/128, 256, G1_SMEM>>>(x, W);
    k_out<<<B_ROWS/128, 256, KO_SMEM>>>(bias, out);
}